// round 9
// baseline (speedup 1.0000x reference)
#include <cuda_runtime.h>
#include <stdint.h>

#define NP   8192
#define MM   4096
#define BB   4
#define KK   64
#define CIN  64
#define FDIM 67
#define H1D  64
#define H2D  128
#define CAP  512
#define NWORK 144

// exact same constant the reference compares against: f32(0.2*0.2 in double)
#define R2C ((float)(0.2 * 0.2))

// -------- scratch (device globals; no allocation allowed) --------
__device__ float  g_q[BB * MM * 3];
__device__ int    g_prog[BB];
__device__ float4 g_sort[BB * NP];     // Morton-scatter staging (x,y,z,idx-bits)

// -------- packed f32x2 helpers (per-lane IEEE, bit-identical to scalar) -----
typedef unsigned long long u64;
__device__ __forceinline__ u64 pack2(float lo, float hi) {
    u64 r; asm("mov.b64 %0, {%1, %2};" : "=l"(r) : "f"(lo), "f"(hi)); return r;
}
__device__ __forceinline__ void unpack2(u64 v, float& lo, float& hi) {
    asm("mov.b64 {%0, %1}, %2;" : "=f"(lo), "=f"(hi) : "l"(v));
}
__device__ __forceinline__ u64 add2(u64 a, u64 b) {
    u64 r; asm("add.rn.f32x2 %0, %1, %2;" : "=l"(r) : "l"(a), "l"(b)); return r;
}
__device__ __forceinline__ u64 mul2(u64 a, u64 b) {
    u64 r; asm("mul.rn.f32x2 %0, %1, %2;" : "=l"(r) : "l"(a), "l"(b)); return r;
}
__device__ __forceinline__ u64 fma2(u64 a, u64 b, u64 c) {
    u64 r; asm("fma.rn.f32x2 %0, %1, %2, %3;" : "=l"(r) : "l"(a), "l"(b), "l"(c)); return r;
}
__device__ __forceinline__ unsigned redux_max(unsigned v) {
    unsigned r; asm("redux.sync.max.u32 %0, %1, 0xffffffff;" : "=r"(r) : "r"(v)); return r;
}
__device__ __forceinline__ u64 shfl_xor64(u64 v, int m) {
    unsigned lo = (unsigned)v, hi = (unsigned)(v >> 32);
    lo = __shfl_xor_sync(0xffffffffu, lo, m);
    hi = __shfl_xor_sync(0xffffffffu, hi, m);
    return ((u64)hi << 32) | (u64)lo;
}
__device__ __forceinline__ int spread3(int v) {
    return (v & 1) | ((v & 2) << 2) | ((v & 4) << 4);
}
__device__ __forceinline__ int cell_of(float px, float py, float pz) {
    int cx = min(7, max(0, (int)(px * 8.0f)));
    int cy = min(7, max(0, (int)(py * 8.0f)));
    int cz = min(7, max(0, (int)(pz * 8.0f)));
    return spread3(cx) | (spread3(cy) << 1) | (spread3(cz) << 2);
}

__global__ void reset_kernel() {
    if (threadIdx.x < BB) g_prog[threadIdx.x] = 0;
}

// =====================================================================
// Fused persistent kernel (100KB dynamic smem -> 128KB L1 stays live).
// Blocks 0..3: FPS producer, ONE barrier per step, tree fold of warp keys.
// Blocks 4..147: workers — nanosleep-backoff wait, radius scan (L1-hot
// pos), register/shfl bitonic top-K, float4 gather, FFMA2 MLP, masked max.
// =====================================================================
__global__ void __launch_bounds__(512, 1) fused_kernel(
    const float* __restrict__ x, const float* __restrict__ pos,
    const float* __restrict__ W1, const float* __restrict__ b1,
    const float* __restrict__ W2, const float* __restrict__ b2,
    float* __restrict__ out, int out_size)
{
    extern __shared__ float smf[];
    const int tid = threadIdx.x;

    if (blockIdx.x < BB) {
        // ======================= FPS producer =======================
        float* sxo = smf;                 // [NP] original order
        float* syo = smf + NP;
        float* szo = smf + 2 * NP;
        int* cnt = (int*)(smf + 3 * NP);  // [512]

        __shared__ u64 rv64[2][16];       // per-warp packed (d2 | ~idx), double-buffered
        __shared__ int wsum[16];

        const int b = blockIdx.x;
        const int lane = tid & 31, warp = tid >> 5;
        const float* pb = pos + (size_t)b * NP * 3;

        cnt[tid] = 0;
        __syncthreads();
        for (int i = tid; i < NP; i += 512) {
            float px = pb[3 * i + 0], py = pb[3 * i + 1], pz = pb[3 * i + 2];
            sxo[i] = px; syo[i] = py; szo[i] = pz;
            atomicAdd(&cnt[cell_of(px, py, pz)], 1);
        }
        __syncthreads();

        int myc = cnt[tid];
        int v = myc;
#pragma unroll
        for (int o = 1; o < 32; o <<= 1) {
            int n = __shfl_up_sync(0xffffffffu, v, o);
            if (lane >= o) v += n;
        }
        if (lane == 31) wsum[warp] = v;
        __syncthreads();
        int woff = 0;
#pragma unroll
        for (int j = 0; j < 16; j++) woff += (j < warp) ? wsum[j] : 0;
        const int start = woff + v - myc;
        __syncthreads();
        cnt[tid] = start;
        __syncthreads();

        // scatter into Morton order -> GLOBAL scratch (one-time)
        for (int i = tid; i < NP; i += 512) {
            float px = sxo[i], py = syo[i], pz = szo[i];
            int slot = atomicAdd(&cnt[cell_of(px, py, pz)], 1);
            float4 rec; rec.x = px; rec.y = py; rec.z = pz; rec.w = __int_as_float(i);
            g_sort[b * NP + slot] = rec;
        }
        __syncthreads();   // global writes visible block-wide after bar

        const int base = tid * 16;
        u64 X[8], Y[8], Z[8];
        unsigned idx2[8];
        float lox = 1e30f, loy = 1e30f, loz = 1e30f;
        float hix = -1e30f, hiy = -1e30f, hiz = -1e30f;
#pragma unroll
        for (int i = 0; i < 8; i++) {
            float4 v0 = g_sort[b * NP + base + 2 * i];
            float4 v1 = g_sort[b * NP + base + 2 * i + 1];
            X[i] = pack2(v0.x, v1.x); Y[i] = pack2(v0.y, v1.y); Z[i] = pack2(v0.z, v1.z);
            idx2[i] = (__float_as_uint(v0.w) & 0xFFFFu) | (__float_as_uint(v1.w) << 16);
            lox = fminf(lox, fminf(v0.x, v1.x)); hix = fmaxf(hix, fmaxf(v0.x, v1.x));
            loy = fminf(loy, fminf(v0.y, v1.y)); hiy = fmaxf(hiy, fmaxf(v0.y, v1.y));
            loz = fminf(loz, fminf(v0.z, v1.z)); hiz = fmaxf(hiz, fmaxf(v0.z, v1.z));
        }

        float cx = sxo[0], cy = syo[0], cz = szo[0];
        float d[16];
        float tv = -1.0f;
        {
            u64 ncx = pack2(-cx, -cx), ncy = pack2(-cy, -cy), ncz = pack2(-cz, -cz);
#pragma unroll
            for (int i = 0; i < 8; i++) {
                u64 dx = add2(X[i], ncx);
                u64 dy = add2(Y[i], ncy);
                u64 dz = add2(Z[i], ncz);
                u64 nd = mul2(dx, dx);
                nd = fma2(dy, dy, nd);
                nd = fma2(dz, dz, nd);
                float n0, n1; unpack2(nd, n0, n1);
                d[2 * i + 0] = n0;
                d[2 * i + 1] = n1;
                tv = fmaxf(tv, fmaxf(n0, n1));
            }
        }
        if (tid == 0) {
            g_q[(b * MM) * 3 + 0] = cx;
            g_q[(b * MM) * 3 + 1] = cy;
            g_q[(b * MM) * 3 + 2] = cz;
        }

        for (int t = 1; t < MM; t++) {
            // per-warp: max d2 + min orig index achieving it (2 redux + rare scan)
            const unsigned tb = __float_as_uint(tv);
            const unsigned wmax = redux_max(tb);
            unsigned inv = 0;
            if (tb == wmax) {                               // candidate lane only
                const float vm = __uint_as_float(wmax);
                unsigned lm = 0xFFFFFFFFu;
#pragma unroll
                for (int i = 0; i < 16; i++)
                    if (d[i] == vm) {
                        unsigned orig = (idx2[i >> 1] >> ((i & 1) * 16)) & 0xFFFFu;
                        lm = min(lm, orig);
                    }
                inv = 0xFFFFFFFFu - lm;
            }
            const unsigned invmax = redux_max(inv);
            const int buf = t & 1;
            if (lane == 0) rv64[buf][warp] = ((u64)wmax << 32) | (u64)invmax;
            __syncthreads();                                // ONE bar per step

            // depth-4 tree fold: max d2, tie -> min orig idx (exact, ILP)
            u64 a0 = max(rv64[buf][0],  rv64[buf][1]);
            u64 a1 = max(rv64[buf][2],  rv64[buf][3]);
            u64 a2 = max(rv64[buf][4],  rv64[buf][5]);
            u64 a3 = max(rv64[buf][6],  rv64[buf][7]);
            u64 a4 = max(rv64[buf][8],  rv64[buf][9]);
            u64 a5 = max(rv64[buf][10], rv64[buf][11]);
            u64 a6 = max(rv64[buf][12], rv64[buf][13]);
            u64 a7 = max(rv64[buf][14], rv64[buf][15]);
            u64 b0 = max(a0, a1), b1v = max(a2, a3);
            u64 b2v = max(a4, a5), b3 = max(a6, a7);
            u64 best = max(max(b0, b1v), max(b2v, b3));
            const int w = (int)(0xFFFFFFFFu - (unsigned)best);

            cx = sxo[w]; cy = syo[w]; cz = szo[w];
            if (tid == 0) {
                g_q[(b * MM + t) * 3 + 0] = cx;
                g_q[(b * MM + t) * 3 + 1] = cy;
                g_q[(b * MM + t) * 3 + 2] = cz;
                if ((t & 7) == 7 || t == MM - 1) {
                    __threadfence();
                    *(volatile int*)&g_prog[b] = t + 1;
                }
            }

            // bbox lower-bound distance: skip update if it can't lower any d
            float ddx = fmaxf(fmaxf(lox - cx, cx - hix), 0.0f);
            float ddy = fmaxf(fmaxf(loy - cy, cy - hiy), 0.0f);
            float ddz = fmaxf(fmaxf(loz - cz, cz - hiz), 0.0f);
            float dm2 = ddx * ddx;
            dm2 = fmaf(ddy, ddy, dm2);
            dm2 = fmaf(ddz, ddz, dm2);

            if (dm2 * 0.99999f < tv) {
                u64 ncx = pack2(-cx, -cx), ncy = pack2(-cy, -cy), ncz = pack2(-cz, -cz);
                float ntv = -1.0f;
#pragma unroll
                for (int i = 0; i < 8; i++) {
                    u64 dx = add2(X[i], ncx);
                    u64 dy = add2(Y[i], ncy);
                    u64 dz = add2(Z[i], ncz);
                    u64 nd = mul2(dx, dx);
                    nd = fma2(dy, dy, nd);
                    nd = fma2(dz, dz, nd);
                    float n0, n1; unpack2(nd, n0, n1);
                    float d0 = fminf(d[2 * i + 0], n0);
                    float d1 = fminf(d[2 * i + 1], n1);
                    d[2 * i + 0] = d0;
                    d[2 * i + 1] = d1;
                    ntv = fmaxf(ntv, fmaxf(d0, d1));
                }
                tv = ntv;
            }
        }
        return;
    }

    // ======================= worker =======================
    float* W1s  = smf;               // 67*64 = 4288
    float* b1s  = smf + 4288;        // 64
    float* W2s  = smf + 4352;        // 64*128 = 8192
    float* b2s  = smf + 12544;       // 128
    float* feat = smf + 12672;       // 64*68 = 4352
    float* h1s  = smf + 17024;       // 64*68 = 4352
    float* pmax = smf + 21376;       // 16*128 = 2048
    u64*   keys = (u64*)(smf + 23424);   // 512 * 8B -> ends 97792B

    __shared__ float qs[3];
    __shared__ int scnt2[2];

    for (int i = tid; i < FDIM * H1D; i += 512) W1s[i] = W1[i];
    for (int i = tid; i < H1D * H2D; i += 512) W2s[i] = W2[i];
    if (tid < H1D) b1s[tid] = b1[tid];
    if (tid < H2D) b2s[tid] = b2[tid];
    if (tid < 2) scnt2[tid] = 0;

    const int wb = (int)blockIdx.x - BB;
    const int b = wb & 3;                        // fixed cloud per block (144 % 4 == 0)
    const float* pb = pos + (size_t)b * NP * 3;
    const float4* xb4 = (const float4*)(x + (size_t)b * NP * CIN);
    int kk = 0;
    for (int ii = wb; ii < BB * MM; ii += NWORK, kk++) {
        const int t = ii >> 2;
        const int c = b * MM + t;

        if (tid == 0) {
            while (*(volatile int*)&g_prog[b] < t + 1) { __nanosleep(256); }
            __threadfence();
            qs[0] = __ldcg(&g_q[c * 3 + 0]);
            qs[1] = __ldcg(&g_q[c * 3 + 1]);
            qs[2] = __ldcg(&g_q[c * 3 + 2]);
        }
        __syncthreads();                              // A
        const float qx = qs[0], qy = qs[1], qz = qs[2];

        const int par = kk & 1;
        int* cntp = &scnt2[par];
#pragma unroll 4
        for (int u = 0; u < 16; u++) {
            int p = tid + 512 * u;
            float px = pb[3 * p + 0], py = pb[3 * p + 1], pz = pb[3 * p + 2];
            float dx = qx - px, dy = qy - py, dz = qz - pz;
            float d2 = dx * dx + dy * dy + dz * dz;
            if (d2 <= R2C) {
                int s = atomicAdd(cntp, 1);
                if (s < CAP) keys[s] = ((u64)__float_as_uint(d2) << 32) | (unsigned)p;
            }
        }
        __syncthreads();                              // B
        const int n = min(*cntp, CAP);
        if (tid == 0) scnt2[par ^ 1] = 0;             // reset other buffer

        // -------- register/shfl bitonic sort, 512 keys ascending --------
        u64 key = (tid < n) ? keys[tid] : 0xFFFFFFFFFFFFFFFFull;
#pragma unroll
        for (int k2 = 2; k2 <= CAP; k2 <<= 1) {
#pragma unroll
            for (int j = k2 >> 1; j > 0; j >>= 1) {
                const bool asc = ((tid & k2) == 0);
                u64 other;
                if (j >= 32) {
                    __syncthreads();
                    keys[tid] = key;
                    __syncthreads();
                    other = keys[tid ^ j];
                } else {
                    other = shfl_xor64(key, j);
                }
                const bool lower = ((tid & j) == 0);
                const bool keepMin = (lower == asc);
                const bool less = key < other;
                key = (less == keepMin) ? key : other;
            }
        }
        __syncthreads();
        keys[tid] = key;
        __syncthreads();                              // C
        const int m = min(n, KK);

        // -------- gather features (float4) --------
#pragma unroll
        for (int u = 0; u < 2; u++) {
            int q = tid + 512 * u;                    // 0..1023
            int j = q >> 4, c4 = q & 15;
            int row = (j < m) ? (int)(keys[j] & 0xFFFFFFFFull) : 0;
            float4 vv = xb4[(size_t)row * 16 + c4];
            if (j >= m) { vv.x = 0.0f; vv.y = 0.0f; vv.z = 0.0f; vv.w = 0.0f; }
            *(float4*)&feat[j * 68 + c4 * 4] = vv;
        }
        if (tid < KK) {
            int j = tid;
            int row = (j < m) ? (int)(keys[j] & 0xFFFFFFFFull) : 0;
            const float* pr = pb + (size_t)row * 3;
            feat[j * 68 + 64] = (j < m) ? pr[0] - qx : 0.0f;
            feat[j * 68 + 65] = (j < m) ? pr[1] - qy : 0.0f;
            feat[j * 68 + 66] = (j < m) ? pr[2] - qz : 0.0f;
            feat[j * 68 + 67] = 0.0f;
        }
        __syncthreads();                              // D

        // ---- phase 1: h1[64,64] = relu(feat @ W1 + b1), FFMA2-packed ----
        {
            const int rg = tid >> 4;                  // rows rg*2, rg*2+1
            const int cg = tid & 15;                  // cols cg*4
            float4 bv = *(const float4*)&b1s[cg * 4];
            u64 a0p = pack2(bv.x, bv.y), a0q = pack2(bv.z, bv.w);
            u64 a1p = a0p, a1q = a0q;
            const float* f0p = &feat[(rg * 2 + 0) * 68];
            const float* f1p = &feat[(rg * 2 + 1) * 68];
            for (int k = 0; k < FDIM; k++) {
                float f0 = f0p[k], f1 = f1p[k];
                float4 w = *(const float4*)&W1s[k * 64 + cg * 4];
                u64 w01 = pack2(w.x, w.y), w23 = pack2(w.z, w.w);
                u64 f0v = pack2(f0, f0), f1v = pack2(f1, f1);
                a0p = fma2(f0v, w01, a0p); a0q = fma2(f0v, w23, a0q);
                a1p = fma2(f1v, w01, a1p); a1q = fma2(f1v, w23, a1q);
            }
            float v0, v1, v2, v3;
            float4 h;
            unpack2(a0p, v0, v1); unpack2(a0q, v2, v3);
            h.x = fmaxf(v0, 0.0f); h.y = fmaxf(v1, 0.0f);
            h.z = fmaxf(v2, 0.0f); h.w = fmaxf(v3, 0.0f);
            *(float4*)&h1s[(rg * 2 + 0) * 68 + cg * 4] = h;
            unpack2(a1p, v0, v1); unpack2(a1q, v2, v3);
            h.x = fmaxf(v0, 0.0f); h.y = fmaxf(v1, 0.0f);
            h.z = fmaxf(v2, 0.0f); h.w = fmaxf(v3, 0.0f);
            *(float4*)&h1s[(rg * 2 + 1) * 68 + cg * 4] = h;
        }
        __syncthreads();                              // E

        // ---- phase 2: relu(h1 @ W2 + b2), masked max, FFMA2-packed ----
        {
            const int rg = tid >> 5;                  // rows rg*4..+3
            const int cg = tid & 31;                  // cols cg*4
            float4 bv = *(const float4*)&b2s[cg * 4];
            u64 accp[4], accq[4];
#pragma unroll
            for (int r = 0; r < 4; r++) { accp[r] = pack2(bv.x, bv.y); accq[r] = pack2(bv.z, bv.w); }
            for (int k = 0; k < H1D; k++) {
                float4 w = *(const float4*)&W2s[k * 128 + cg * 4];
                u64 w01 = pack2(w.x, w.y), w23 = pack2(w.z, w.w);
#pragma unroll
                for (int r = 0; r < 4; r++) {
                    float hv = h1s[(rg * 4 + r) * 68 + k];
                    u64 hvv = pack2(hv, hv);
                    accp[r] = fma2(hvv, w01, accp[r]);
                    accq[r] = fma2(hvv, w23, accq[r]);
                }
            }
            float mx0 = -3.402823466e38f, mx1 = mx0, mx2 = mx0, mx3 = mx0;
#pragma unroll
            for (int r = 0; r < 4; r++) {
                if (rg * 4 + r < m) {
                    float v0, v1, v2, v3;
                    unpack2(accp[r], v0, v1); unpack2(accq[r], v2, v3);
                    mx0 = fmaxf(mx0, fmaxf(v0, 0.0f));
                    mx1 = fmaxf(mx1, fmaxf(v1, 0.0f));
                    mx2 = fmaxf(mx2, fmaxf(v2, 0.0f));
                    mx3 = fmaxf(mx3, fmaxf(v3, 0.0f));
                }
            }
            float4 mv; mv.x = mx0; mv.y = mx1; mv.z = mx2; mv.w = mx3;
            *(float4*)&pmax[rg * 128 + cg * 4] = mv;
        }
        __syncthreads();                              // F

        if (tid < H2D) {
            float r = pmax[tid];
#pragma unroll
            for (int g = 1; g < 16; g++) r = fmaxf(r, pmax[g * 128 + tid]);
            if (c * H2D + tid < out_size) out[c * H2D + tid] = r;
        }
        {
            const int PO = BB * MM * H2D;
            const int BO = PO + BB * MM * 3;
            if (tid >= 128 && tid < 131) {
                int k3 = tid - 128;
                if (PO + c * 3 + k3 < out_size) out[PO + c * 3 + k3] = qs[k3];
            }
            if (tid == 131 && BO + c < out_size) out[BO + c] = (float)b;
        }
        __syncthreads();                              // G (smem reuse next iter)
    }
}

// =====================================================================
extern "C" void kernel_launch(void* const* d_in, const int* in_sizes, int n_in,
                              void* d_out, int out_size)
{
    const float* x   = (const float*)d_in[0];
    const float* pos = (const float*)d_in[1];
    const float* W1  = (const float*)d_in[3];
    const float* b1  = (const float*)d_in[4];
    const float* W2  = (const float*)d_in[5];
    const float* b2  = (const float*)d_in[6];
    float* out = (float*)d_out;

    const int FUSED_SMEM = 3 * NP * 4 + 512 * 4;   // 100352 B (FPS layout is the max)
    cudaFuncSetAttribute(fused_kernel, cudaFuncAttributeMaxDynamicSharedMemorySize, FUSED_SMEM);

    reset_kernel<<<1, 32>>>();
    fused_kernel<<<BB + NWORK, 512, FUSED_SMEM>>>(x, pos, W1, b1, W2, b2, out, out_size);
}

// round 10
// speedup vs baseline: 1.0720x; 1.0720x over previous
#include <cuda_runtime.h>
#include <stdint.h>

#define NP   8192
#define MM   4096
#define BB   4
#define KK   64
#define CIN  64
#define FDIM 67
#define H1D  64
#define H2D  128
#define CAP  512
#define NWORK 144
#define NGRP (BB * MM / 4)   // 4096 groups of 4 centroids

// exact same constant the reference compares against: f32(0.2*0.2 in double)
#define R2C ((float)(0.2 * 0.2))

// -------- scratch (device globals; no allocation allowed) --------
__device__ float  g_q[BB * MM * 3];
__device__ int    g_prog[BB];
__device__ float4 g_sort[BB * NP];     // Morton-scatter staging (x,y,z,idx-bits)

// -------- packed f32x2 helpers (per-lane IEEE, bit-identical to scalar) -----
typedef unsigned long long u64;
__device__ __forceinline__ u64 pack2(float lo, float hi) {
    u64 r; asm("mov.b64 %0, {%1, %2};" : "=l"(r) : "f"(lo), "f"(hi)); return r;
}
__device__ __forceinline__ void unpack2(u64 v, float& lo, float& hi) {
    asm("mov.b64 {%0, %1}, %2;" : "=f"(lo), "=f"(hi) : "l"(v));
}
__device__ __forceinline__ u64 add2(u64 a, u64 b) {
    u64 r; asm("add.rn.f32x2 %0, %1, %2;" : "=l"(r) : "l"(a), "l"(b)); return r;
}
__device__ __forceinline__ u64 mul2(u64 a, u64 b) {
    u64 r; asm("mul.rn.f32x2 %0, %1, %2;" : "=l"(r) : "l"(a), "l"(b)); return r;
}
__device__ __forceinline__ u64 fma2(u64 a, u64 b, u64 c) {
    u64 r; asm("fma.rn.f32x2 %0, %1, %2, %3;" : "=l"(r) : "l"(a), "l"(b), "l"(c)); return r;
}
__device__ __forceinline__ unsigned redux_max(unsigned v) {
    unsigned r; asm("redux.sync.max.u32 %0, %1, 0xffffffff;" : "=r"(r) : "r"(v)); return r;
}
__device__ __forceinline__ u64 shfl_xor64(u64 v, int m) {
    unsigned lo = (unsigned)v, hi = (unsigned)(v >> 32);
    lo = __shfl_xor_sync(0xffffffffu, lo, m);
    hi = __shfl_xor_sync(0xffffffffu, hi, m);
    return ((u64)hi << 32) | (u64)lo;
}
__device__ __forceinline__ int spread3(int v) {
    return (v & 1) | ((v & 2) << 2) | ((v & 4) << 4);
}
__device__ __forceinline__ int cell_of(float px, float py, float pz) {
    int cx = min(7, max(0, (int)(px * 8.0f)));
    int cy = min(7, max(0, (int)(py * 8.0f)));
    int cz = min(7, max(0, (int)(pz * 8.0f)));
    return spread3(cx) | (spread3(cy) << 1) | (spread3(cz) << 2);
}

__global__ void reset_kernel() {
    if (threadIdx.x < BB) g_prog[threadIdx.x] = 0;
}

// =====================================================================
// Fused persistent kernel (110KB dynamic smem -> ~117KB L1 keeps the
// worker's pos cloud resident).
// Blocks 0..3: FPS producer (two-bar reduction, atomicMin tie-break —
//   the best-measured variant), publishing g_prog every 16 steps.
// Blocks 4..147: workers — each iteration handles FOUR consecutive
//   centroids of its cloud: one shared radius scan (pos loads amortized
//   4x), then per centroid: register/shfl bitonic top-K, float4 gather,
//   FFMA2 MLP, masked max.
// =====================================================================
__global__ void __launch_bounds__(512, 1) fused_kernel(
    const float* __restrict__ x, const float* __restrict__ pos,
    const float* __restrict__ W1, const float* __restrict__ b1,
    const float* __restrict__ W2, const float* __restrict__ b2,
    float* __restrict__ out, int out_size)
{
    extern __shared__ float smf[];
    const int tid = threadIdx.x;

    if (blockIdx.x < BB) {
        // ======================= FPS producer =======================
        float* sxo = smf;                 // [NP] original order
        float* syo = smf + NP;
        float* szo = smf + 2 * NP;
        int* cnt = (int*)(smf + 3 * NP);  // [512]

        __shared__ unsigned rv[16];
        __shared__ int wsum[16];
        __shared__ int s_widx[2];

        const int b = blockIdx.x;
        const int lane = tid & 31, warp = tid >> 5;
        const float* pb = pos + (size_t)b * NP * 3;

        cnt[tid] = 0;
        if (tid == 0) { s_widx[0] = 0x7FFFFFFF; s_widx[1] = 0x7FFFFFFF; }
        __syncthreads();
        for (int i = tid; i < NP; i += 512) {
            float px = pb[3 * i + 0], py = pb[3 * i + 1], pz = pb[3 * i + 2];
            sxo[i] = px; syo[i] = py; szo[i] = pz;
            atomicAdd(&cnt[cell_of(px, py, pz)], 1);
        }
        __syncthreads();

        int myc = cnt[tid];
        int v = myc;
#pragma unroll
        for (int o = 1; o < 32; o <<= 1) {
            int n = __shfl_up_sync(0xffffffffu, v, o);
            if (lane >= o) v += n;
        }
        if (lane == 31) wsum[warp] = v;
        __syncthreads();
        int woff = 0;
#pragma unroll
        for (int j = 0; j < 16; j++) woff += (j < warp) ? wsum[j] : 0;
        const int start = woff + v - myc;
        __syncthreads();
        cnt[tid] = start;
        __syncthreads();

        // scatter into Morton order -> GLOBAL scratch (one-time)
        for (int i = tid; i < NP; i += 512) {
            float px = sxo[i], py = syo[i], pz = szo[i];
            int slot = atomicAdd(&cnt[cell_of(px, py, pz)], 1);
            float4 rec; rec.x = px; rec.y = py; rec.z = pz; rec.w = __int_as_float(i);
            g_sort[b * NP + slot] = rec;
        }
        __syncthreads();   // global writes visible block-wide after bar

        const int base = tid * 16;
        u64 X[8], Y[8], Z[8];
        unsigned idx2[8];
        float lox = 1e30f, loy = 1e30f, loz = 1e30f;
        float hix = -1e30f, hiy = -1e30f, hiz = -1e30f;
#pragma unroll
        for (int i = 0; i < 8; i++) {
            float4 v0 = g_sort[b * NP + base + 2 * i];
            float4 v1 = g_sort[b * NP + base + 2 * i + 1];
            X[i] = pack2(v0.x, v1.x); Y[i] = pack2(v0.y, v1.y); Z[i] = pack2(v0.z, v1.z);
            idx2[i] = (__float_as_uint(v0.w) & 0xFFFFu) | (__float_as_uint(v1.w) << 16);
            lox = fminf(lox, fminf(v0.x, v1.x)); hix = fmaxf(hix, fmaxf(v0.x, v1.x));
            loy = fminf(loy, fminf(v0.y, v1.y)); hiy = fmaxf(hiy, fmaxf(v0.y, v1.y));
            loz = fminf(loz, fminf(v0.z, v1.z)); hiz = fmaxf(hiz, fmaxf(v0.z, v1.z));
        }

        float cx = sxo[0], cy = syo[0], cz = szo[0];
        float d[16];
        float tv = -1.0f;
        {
            u64 ncx = pack2(-cx, -cx), ncy = pack2(-cy, -cy), ncz = pack2(-cz, -cz);
#pragma unroll
            for (int i = 0; i < 8; i++) {
                u64 dx = add2(X[i], ncx);
                u64 dy = add2(Y[i], ncy);
                u64 dz = add2(Z[i], ncz);
                u64 nd = mul2(dx, dx);
                nd = fma2(dy, dy, nd);
                nd = fma2(dz, dz, nd);
                float n0, n1; unpack2(nd, n0, n1);
                d[2 * i + 0] = n0;
                d[2 * i + 1] = n1;
                tv = fmaxf(tv, fmaxf(n0, n1));
            }
        }
        if (tid == 0) {
            g_q[(b * MM) * 3 + 0] = cx;
            g_q[(b * MM) * 3 + 1] = cy;
            g_q[(b * MM) * 3 + 2] = cz;
        }

        for (int t = 1; t < MM; t++) {
            // block max of tv via u32 redux (d2 >= 0 -> bit order == float order)
            const unsigned tb = __float_as_uint(tv);
            unsigned wmax = redux_max(tb);
            if (lane == 0) rv[warp] = wmax;
            __syncthreads();                                  // (A)

            unsigned vmb = rv[0];
#pragma unroll
            for (int j = 1; j < 16; j++) vmb = max(vmb, rv[j]);
            const float vm = __uint_as_float(vmb);

            const int cur = t & 1;
            if (tb == vmb) {                                  // only potential winners
#pragma unroll
                for (int i = 0; i < 16; i++)
                    if (d[i] == vm) {
                        int orig = (int)((idx2[i >> 1] >> ((i & 1) * 16)) & 0xFFFFu);
                        atomicMin(&s_widx[cur], orig);        // reference tie-break
                    }
            }
            if (tid == 0) s_widx[cur ^ 1] = 0x7FFFFFFF;       // pre-reset other buffer
            __syncthreads();                                  // (B)

            const int w = s_widx[cur];                        // original index
            cx = sxo[w]; cy = syo[w]; cz = szo[w];
            if (tid == 0) {
                g_q[(b * MM + t) * 3 + 0] = cx;
                g_q[(b * MM + t) * 3 + 1] = cy;
                g_q[(b * MM + t) * 3 + 2] = cz;
                if ((t & 15) == 15 || t == MM - 1) {
                    __threadfence();
                    *(volatile int*)&g_prog[b] = t + 1;
                }
            }

            // bbox lower-bound distance: skip update if it can't lower any d
            float ddx = fmaxf(fmaxf(lox - cx, cx - hix), 0.0f);
            float ddy = fmaxf(fmaxf(loy - cy, cy - hiy), 0.0f);
            float ddz = fmaxf(fmaxf(loz - cz, cz - hiz), 0.0f);
            float dm2 = ddx * ddx;
            dm2 = fmaf(ddy, ddy, dm2);
            dm2 = fmaf(ddz, ddz, dm2);

            if (dm2 * 0.99999f < tv) {
                u64 ncx = pack2(-cx, -cx), ncy = pack2(-cy, -cy), ncz = pack2(-cz, -cz);
                float ntv = -1.0f;
#pragma unroll
                for (int i = 0; i < 8; i++) {
                    u64 dx = add2(X[i], ncx);
                    u64 dy = add2(Y[i], ncy);
                    u64 dz = add2(Z[i], ncz);
                    u64 nd = mul2(dx, dx);
                    nd = fma2(dy, dy, nd);
                    nd = fma2(dz, dz, nd);
                    float n0, n1; unpack2(nd, n0, n1);
                    float d0 = fminf(d[2 * i + 0], n0);
                    float d1 = fminf(d[2 * i + 1], n1);
                    d[2 * i + 0] = d0;
                    d[2 * i + 1] = d1;
                    ntv = fmaxf(ntv, fmaxf(d0, d1));
                }
                tv = ntv;
            }
        }
        return;
    }

    // ======================= worker =======================
    float* W1s  = smf;               // 67*64 = 4288
    float* b1s  = smf + 4288;        // 64
    float* W2s  = smf + 4352;        // 64*128 = 8192
    float* b2s  = smf + 12544;       // 128
    float* feat = smf + 12672;       // 64*68 = 4352
    float* h1s  = smf + 17024;       // 64*68 = 4352
    float* pmax = smf + 21376;       // 16*128 = 2048
    u64*   keys4 = (u64*)(smf + 23424);  // 4 x 512 u64 = 16KB -> ends 110080B

    __shared__ float qs[4][3];
    __shared__ int cnt8[2][4];

    for (int i = tid; i < FDIM * H1D; i += 512) W1s[i] = W1[i];
    for (int i = tid; i < H1D * H2D; i += 512) W2s[i] = W2[i];
    if (tid < H1D) b1s[tid] = b1[tid];
    if (tid < H2D) b2s[tid] = b2[tid];
    if (tid < 8) cnt8[tid >> 2][tid & 3] = 0;

    const int wb = (int)blockIdx.x - BB;
    const int b = wb & 3;                        // fixed cloud per block (144 % 4 == 0)
    const float* pb = pos + (size_t)b * NP * 3;
    const float4* xb4 = (const float4*)(x + (size_t)b * NP * CIN);
    int kk = 0;
    for (int g = wb; g < NGRP; g += NWORK, kk++) {
        const int tbase = (g >> 2) * 4;          // 4 consecutive centroids of cloud b
        const int par = kk & 1;

        if (tid == 0) {
            while (*(volatile int*)&g_prog[b] < tbase + 4) { }
            __threadfence();
#pragma unroll
            for (int cc = 0; cc < 4; cc++) {
                int c = b * MM + tbase + cc;
                qs[cc][0] = __ldcg(&g_q[c * 3 + 0]);
                qs[cc][1] = __ldcg(&g_q[c * 3 + 1]);
                qs[cc][2] = __ldcg(&g_q[c * 3 + 2]);
            }
        }
        __syncthreads();                              // A
        const float q0x = qs[0][0], q0y = qs[0][1], q0z = qs[0][2];
        const float q1x = qs[1][0], q1y = qs[1][1], q1z = qs[1][2];
        const float q2x = qs[2][0], q2y = qs[2][1], q2z = qs[2][2];
        const float q3x = qs[3][0], q3y = qs[3][1], q3z = qs[3][2];

        // -------- shared radius scan: 1 pass of pos, 4 centroids --------
        int* cntp = &cnt8[par][0];
#pragma unroll 4
        for (int u = 0; u < 16; u++) {
            int p = tid + 512 * u;
            float px = pb[3 * p + 0], py = pb[3 * p + 1], pz = pb[3 * p + 2];
            {
                float dx = q0x - px, dy = q0y - py, dz = q0z - pz;
                float d2 = dx * dx + dy * dy + dz * dz;
                if (d2 <= R2C) { int s = atomicAdd(&cntp[0], 1);
                    if (s < CAP) keys4[0 * CAP + s] = ((u64)__float_as_uint(d2) << 32) | (unsigned)p; }
            }
            {
                float dx = q1x - px, dy = q1y - py, dz = q1z - pz;
                float d2 = dx * dx + dy * dy + dz * dz;
                if (d2 <= R2C) { int s = atomicAdd(&cntp[1], 1);
                    if (s < CAP) keys4[1 * CAP + s] = ((u64)__float_as_uint(d2) << 32) | (unsigned)p; }
            }
            {
                float dx = q2x - px, dy = q2y - py, dz = q2z - pz;
                float d2 = dx * dx + dy * dy + dz * dz;
                if (d2 <= R2C) { int s = atomicAdd(&cntp[2], 1);
                    if (s < CAP) keys4[2 * CAP + s] = ((u64)__float_as_uint(d2) << 32) | (unsigned)p; }
            }
            {
                float dx = q3x - px, dy = q3y - py, dz = q3z - pz;
                float d2 = dx * dx + dy * dy + dz * dz;
                if (d2 <= R2C) { int s = atomicAdd(&cntp[3], 1);
                    if (s < CAP) keys4[3 * CAP + s] = ((u64)__float_as_uint(d2) << 32) | (unsigned)p; }
            }
        }
        __syncthreads();                              // B
        if (tid < 4) cnt8[par ^ 1][tid] = 0;          // reset other buffer

        // -------- per centroid: sort + gather + MLP + outputs --------
        for (int cc = 0; cc < 4; cc++) {
            const int c = b * MM + tbase + cc;
            const int n = min(cnt8[par][cc], CAP);
            u64* keyc = keys4 + cc * CAP;

            // register/shfl bitonic sort, 512 keys ascending
            u64 key = (tid < n) ? keyc[tid] : 0xFFFFFFFFFFFFFFFFull;
#pragma unroll
            for (int k2 = 2; k2 <= CAP; k2 <<= 1) {
#pragma unroll
                for (int j = k2 >> 1; j > 0; j >>= 1) {
                    const bool asc = ((tid & k2) == 0);
                    u64 other;
                    if (j >= 32) {
                        __syncthreads();
                        keyc[tid] = key;
                        __syncthreads();
                        other = keyc[tid ^ j];
                    } else {
                        other = shfl_xor64(key, j);
                    }
                    const bool lower = ((tid & j) == 0);
                    const bool keepMin = (lower == asc);
                    const bool less = key < other;
                    key = (less == keepMin) ? key : other;
                }
            }
            __syncthreads();
            keyc[tid] = key;
            __syncthreads();                          // C
            const int m = min(n, KK);

            // gather features (float4)
#pragma unroll
            for (int u = 0; u < 2; u++) {
                int q = tid + 512 * u;                // 0..1023
                int j = q >> 4, c4 = q & 15;
                int row = (j < m) ? (int)(keyc[j] & 0xFFFFFFFFull) : 0;
                float4 vv = xb4[(size_t)row * 16 + c4];
                if (j >= m) { vv.x = 0.0f; vv.y = 0.0f; vv.z = 0.0f; vv.w = 0.0f; }
                *(float4*)&feat[j * 68 + c4 * 4] = vv;
            }
            if (tid < KK) {
                int j = tid;
                int row = (j < m) ? (int)(keyc[j] & 0xFFFFFFFFull) : 0;
                const float* pr = pb + (size_t)row * 3;
                feat[j * 68 + 64] = (j < m) ? pr[0] - qs[cc][0] : 0.0f;
                feat[j * 68 + 65] = (j < m) ? pr[1] - qs[cc][1] : 0.0f;
                feat[j * 68 + 66] = (j < m) ? pr[2] - qs[cc][2] : 0.0f;
                feat[j * 68 + 67] = 0.0f;
            }
            __syncthreads();                          // D

            // phase 1: h1[64,64] = relu(feat @ W1 + b1), FFMA2-packed
            {
                const int rg = tid >> 4;              // rows rg*2, rg*2+1
                const int cg = tid & 15;              // cols cg*4
                float4 bv = *(const float4*)&b1s[cg * 4];
                u64 a0p = pack2(bv.x, bv.y), a0q = pack2(bv.z, bv.w);
                u64 a1p = a0p, a1q = a0q;
                const float* f0p = &feat[(rg * 2 + 0) * 68];
                const float* f1p = &feat[(rg * 2 + 1) * 68];
                for (int k = 0; k < FDIM; k++) {
                    float f0 = f0p[k], f1 = f1p[k];
                    float4 w = *(const float4*)&W1s[k * 64 + cg * 4];
                    u64 w01 = pack2(w.x, w.y), w23 = pack2(w.z, w.w);
                    u64 f0v = pack2(f0, f0), f1v = pack2(f1, f1);
                    a0p = fma2(f0v, w01, a0p); a0q = fma2(f0v, w23, a0q);
                    a1p = fma2(f1v, w01, a1p); a1q = fma2(f1v, w23, a1q);
                }
                float v0, v1, v2, v3;
                float4 h;
                unpack2(a0p, v0, v1); unpack2(a0q, v2, v3);
                h.x = fmaxf(v0, 0.0f); h.y = fmaxf(v1, 0.0f);
                h.z = fmaxf(v2, 0.0f); h.w = fmaxf(v3, 0.0f);
                *(float4*)&h1s[(rg * 2 + 0) * 68 + cg * 4] = h;
                unpack2(a1p, v0, v1); unpack2(a1q, v2, v3);
                h.x = fmaxf(v0, 0.0f); h.y = fmaxf(v1, 0.0f);
                h.z = fmaxf(v2, 0.0f); h.w = fmaxf(v3, 0.0f);
                *(float4*)&h1s[(rg * 2 + 1) * 68 + cg * 4] = h;
            }
            __syncthreads();                          // E

            // phase 2: relu(h1 @ W2 + b2), masked max, FFMA2-packed
            {
                const int rg = tid >> 5;              // rows rg*4..+3
                const int cg = tid & 31;              // cols cg*4
                float4 bv = *(const float4*)&b2s[cg * 4];
                u64 accp[4], accq[4];
#pragma unroll
                for (int r = 0; r < 4; r++) { accp[r] = pack2(bv.x, bv.y); accq[r] = pack2(bv.z, bv.w); }
                for (int k = 0; k < H1D; k++) {
                    float4 w = *(const float4*)&W2s[k * 128 + cg * 4];
                    u64 w01 = pack2(w.x, w.y), w23 = pack2(w.z, w.w);
#pragma unroll
                    for (int r = 0; r < 4; r++) {
                        float hv = h1s[(rg * 4 + r) * 68 + k];
                        u64 hvv = pack2(hv, hv);
                        accp[r] = fma2(hvv, w01, accp[r]);
                        accq[r] = fma2(hvv, w23, accq[r]);
                    }
                }
                float mx0 = -3.402823466e38f, mx1 = mx0, mx2 = mx0, mx3 = mx0;
#pragma unroll
                for (int r = 0; r < 4; r++) {
                    if (rg * 4 + r < m) {
                        float v0, v1, v2, v3;
                        unpack2(accp[r], v0, v1); unpack2(accq[r], v2, v3);
                        mx0 = fmaxf(mx0, fmaxf(v0, 0.0f));
                        mx1 = fmaxf(mx1, fmaxf(v1, 0.0f));
                        mx2 = fmaxf(mx2, fmaxf(v2, 0.0f));
                        mx3 = fmaxf(mx3, fmaxf(v3, 0.0f));
                    }
                }
                float4 mv; mv.x = mx0; mv.y = mx1; mv.z = mx2; mv.w = mx3;
                *(float4*)&pmax[rg * 128 + cg * 4] = mv;
            }
            __syncthreads();                          // F

            if (tid < H2D) {
                float r = pmax[tid];
#pragma unroll
                for (int gg = 1; gg < 16; gg++) r = fmaxf(r, pmax[gg * 128 + tid]);
                if (c * H2D + tid < out_size) out[c * H2D + tid] = r;
            }
            {
                const int PO = BB * MM * H2D;
                const int BO = PO + BB * MM * 3;
                if (tid >= 128 && tid < 131) {
                    int k3 = tid - 128;
                    if (PO + c * 3 + k3 < out_size) out[PO + c * 3 + k3] = qs[cc][k3];
                }
                if (tid == 131 && BO + c < out_size) out[BO + c] = (float)b;
            }
            __syncthreads();                          // G (smem reuse next centroid)
        }
    }
}

// =====================================================================
extern "C" void kernel_launch(void* const* d_in, const int* in_sizes, int n_in,
                              void* d_out, int out_size)
{
    const float* x   = (const float*)d_in[0];
    const float* pos = (const float*)d_in[1];
    const float* W1  = (const float*)d_in[3];
    const float* b1  = (const float*)d_in[4];
    const float* W2  = (const float*)d_in[5];
    const float* b2  = (const float*)d_in[6];
    float* out = (float*)d_out;

    const int FUSED_SMEM = 110080;   // worker layout is the max (keys4 ends at 110080B)
    cudaFuncSetAttribute(fused_kernel, cudaFuncAttributeMaxDynamicSharedMemorySize, FUSED_SMEM);

    reset_kernel<<<1, 32>>>();
    fused_kernel<<<BB + NWORK, 512, FUSED_SMEM>>>(x, pos, W1, b1, W2, b2, out, out_size);
}